// round 7
// baseline (speedup 1.0000x reference)
#include <cuda_runtime.h>
#include <cuda_fp16.h>
#include <cstdint>
#include <cstddef>

#define DI __device__ __forceinline__

// ---------------- problem constants ----------------
static constexpr int DIN   = 4096;
static constexpr int DOUT  = 4096;
static constexpr int MROWS = 8192;          // B*S = 4*2048

// ---------------- GEMM tiling (mma.sync path — tcgen05 is 'a'-gated, harness targets sm_103) ----
static constexpr int BM = 128;
static constexpr int BN = 128;
static constexpr int BK = 64;               // 128B fp16 rows
static constexpr int THREADS = 128;         // 4 warps: 2(M) x 2(N), warp tile 64x64
static constexpr int STAGES = 3;
static constexpr int STAGE_BYTES = (BM + BN) * BK * 2;      // 32 KB
static constexpr int SMEM_BYTES  = STAGES * STAGE_BYTES;    // 96 KB
static constexpr int NCH = DIN / BK;        // 64 K-chunks
static constexpr int MT_TILES = MROWS / BM; // 64
static constexpr int NT_TILES = DOUT / BN;  // 32

// ---------------- device scratch (no allocations allowed) ----------------
__device__ __align__(128) __half g_A[(size_t)MROWS * DIN];   // 64 MB fp16 x
__device__ __align__(128) __half g_Wt[(size_t)DOUT * DIN];   // 32 MB fp16 ternary {-1,0,1}
__device__ float    g_bt[DOUT];
__device__ unsigned g_maxbits;

// ---------------- helpers ----------------
DI uint32_t smem_u32(const void* p) {
    uint32_t a;
    asm("{ .reg .u64 t; cvta.to.shared.u64 t, %1; cvt.u32.u64 %0, t; }"
        : "=r"(a) : "l"(p));
    return a;
}
DI uint32_t swz(uint32_t off) { return off ^ ((off >> 3) & 0x70); }  // SW128

DI void cp_async16(uint32_t saddr, const void* gaddr) {
    asm volatile("cp.async.cg.shared.global [%0], [%1], 16;" :: "r"(saddr), "l"(gaddr));
}

#define LDSM4(r0, r1, r2, r3, addr) \
    asm volatile("ldmatrix.sync.aligned.m8n8.x4.shared.b16 {%0,%1,%2,%3}, [%4];" \
                 : "=r"(r0), "=r"(r1), "=r"(r2), "=r"(r3) : "r"(addr))

DI void mma16816(float* c, const uint32_t* a, uint32_t b0, uint32_t b1) {
    asm volatile(
        "mma.sync.aligned.m16n8k16.row.col.f32.f16.f16.f32 "
        "{%0,%1,%2,%3}, {%4,%5,%6,%7}, {%8,%9}, {%0,%1,%2,%3};"
        : "+f"(c[0]), "+f"(c[1]), "+f"(c[2]), "+f"(c[3])
        : "r"(a[0]), "r"(a[1]), "r"(a[2]), "r"(a[3]), "r"(b0), "r"(b1));
}

// ---------------- prep kernels ----------------
__global__ void k_init() {
    if (threadIdx.x == 0) g_maxbits = 0u;
}

__global__ void k_absmax(const float4* __restrict__ W, int n4) {
    int tid = threadIdx.x;
    float m = 0.f;
    for (int i = blockIdx.x * blockDim.x + tid; i < n4; i += gridDim.x * blockDim.x) {
        float4 v = W[i];
        m = fmaxf(m, fmaxf(fmaxf(fabsf(v.x), fabsf(v.y)), fmaxf(fabsf(v.z), fabsf(v.w))));
    }
    #pragma unroll
    for (int o = 16; o; o >>= 1) m = fmaxf(m, __shfl_xor_sync(0xffffffffu, m, o));
    __shared__ float sred[8];
    if ((tid & 31) == 0) sred[tid >> 5] = m;
    __syncthreads();
    if (tid == 0) {
        float mm = sred[0];
        #pragma unroll
        for (int w = 1; w < 8; ++w) mm = fmaxf(mm, sred[w]);
        atomicMax(&g_maxbits, __float_as_uint(mm));  // |.| >= 0 -> uint order == float order
    }
}

DI unsigned tern16(float v, float d) {
    return v > d ? 0x3C00u : (v < -d ? 0xBC00u : 0u);  // +1h / -1h / 0h
}
DI unsigned tpack(float x, float y, float d) {
    return tern16(x, d) | (tern16(y, d) << 16);
}

__global__ void k_tern(const float4* __restrict__ W) {
    const float d = 0.05f * __uint_as_float(g_maxbits);
    size_t i = (size_t)blockIdx.x * blockDim.x + threadIdx.x;
    float4 a = W[2 * i], c = W[2 * i + 1];
    uint4 o;
    o.x = tpack(a.x, a.y, d);
    o.y = tpack(a.z, a.w, d);
    o.z = tpack(c.x, c.y, d);
    o.w = tpack(c.z, c.w, d);
    reinterpret_cast<uint4*>(g_Wt)[i] = o;
}

DI unsigned pack2h(float x, float y) {
    __half2 h = __floats2half2_rn(x, y);
    return *reinterpret_cast<unsigned*>(&h);
}

__global__ void k_convx(const float4* __restrict__ X) {
    size_t i = (size_t)blockIdx.x * blockDim.x + threadIdx.x;
    float4 a = X[2 * i], c = X[2 * i + 1];
    uint4 o;
    o.x = pack2h(a.x, a.y);
    o.y = pack2h(a.z, a.w);
    o.z = pack2h(c.x, c.y);
    o.w = pack2h(c.z, c.w);
    reinterpret_cast<uint4*>(g_A)[i] = o;
}

__global__ void k_bt(const float* __restrict__ b, const float* __restrict__ bscale) {
    __shared__ float red[1024];
    int tid = threadIdx.x;
    float v[4];
    float m = 0.f;
    #pragma unroll
    for (int k = 0; k < 4; ++k) {
        v[k] = b[tid + k * 1024];
        m = fmaxf(m, fabsf(v[k]));
    }
    red[tid] = m;
    __syncthreads();
    for (int off = 512; off > 0; off >>= 1) {
        if (tid < off) red[tid] = fmaxf(red[tid], red[tid + off]);
        __syncthreads();
    }
    const float d = 0.05f * red[0];
    const float s = *bscale;
    #pragma unroll
    for (int k = 0; k < 4; ++k)
        g_bt[tid + k * 1024] = v[k] > d ? s : (v[k] < -d ? -s : 0.f);
}

// ---------------- GEMM: 128x128x64, 4 warps, warp tile 64x64 ------------------
// 3-stage cp.async smem pipeline + 2-deep register fragment pipeline over ks.
__global__ void __launch_bounds__(THREADS, 2)
k_gemm(const float* __restrict__ wscale, float* __restrict__ out) {
    extern __shared__ char smem[];
    const uint32_t sb = smem_u32(smem);
    const int tid  = threadIdx.x;
    const int lane = tid & 31;
    const int warp = tid >> 5;
    const int wm   = warp >> 1;   // 0..1  (M)
    const int wn   = warp & 1;    // 0..1  (N)
    const int nt   = blockIdx.x & (NT_TILES - 1);
    const int mt   = blockIdx.x >> 5;

    const __half* Ab = g_A  + (size_t)mt * BM * DIN;
    const __half* Bb = g_Wt + (size_t)nt * BN * DIN;

    // per-thread ldmatrix base offsets (validated in R5/R6)
    const int lrA = lane & 15;                              // A row within m16
    const int lhA = (lane >> 4) * 16;                       // A k-byte half (0/16)
    const int nB  = ((lane >> 4) & 1) * 8 + (lane & 7);     // B row (n) within n16
    const int kB  = ((lane >> 3) & 1) * 16;                 // B k-byte half

    // swizzled intra-stage offsets for each m2/p, per ks (ks adds +32 bytes pre-swizzle)
    uint32_t offA0[4], offB0[4];
    #pragma unroll
    for (int m2 = 0; m2 < 4; ++m2)
        offA0[m2] = (uint32_t)(wm * 64 + m2 * 16 + lrA) * 128 + lhA;
    #pragma unroll
    for (int p = 0; p < 4; ++p)
        offB0[p] = (uint32_t)(wn * 64 + p * 16 + nB) * 128 + kB;

    float acc[4][8][4];                                     // [m16][n8][frag]
    #pragma unroll
    for (int i = 0; i < 4; ++i)
        #pragma unroll
        for (int j = 0; j < 8; ++j)
            #pragma unroll
            for (int k = 0; k < 4; ++k) acc[i][j][k] = 0.f;

    auto issue_loads = [&](int s, int k0) {
        const uint32_t stg = sb + s * STAGE_BYTES;
        #pragma unroll
        for (int i = 0; i < 16; ++i) {
            int c = tid + i * THREADS;          // 0..2047 16B-chunks per stage
            int row = (c >> 3) & 127;
            int k8  = c & 7;
            const __half* gp;
            uint32_t bufo;
            if (c < 1024) { gp = Ab + (size_t)row * DIN + k0 + k8 * 8; bufo = 0; }
            else          { gp = Bb + (size_t)row * DIN + k0 + k8 * 8; bufo = BM * BK * 2; }
            cp_async16(stg + bufo + swz(row * 128 + k8 * 16), gp);
        }
    };

    // prefetch STAGES-1 stages
    #pragma unroll
    for (int s = 0; s < STAGES - 1; ++s) {
        issue_loads(s, s * BK);
        asm volatile("cp.async.commit_group;" ::: "memory");
    }

    uint32_t afr[2][4][4];     // [buf][m2][4]
    uint32_t bfr[2][4][4];     // [buf][p][4]

    for (int it = 0; it < NCH; ++it) {
        asm volatile("cp.async.wait_group %0;" :: "n"(STAGES - 2) : "memory");
        __syncthreads();   // stage 'it' ready everywhere; all warps past compute(it-1)

        int nx = it + STAGES - 1;
        if (nx < NCH) issue_loads(nx % STAGES, nx * BK);
        asm volatile("cp.async.commit_group;" ::: "memory");

        const uint32_t sA = sb + (it % STAGES) * STAGE_BYTES;
        const uint32_t sB = sA + BM * BK * 2;

        // preload ks=0 fragments into buffer 0
        #pragma unroll
        for (int m2 = 0; m2 < 4; ++m2)
            LDSM4(afr[0][m2][0], afr[0][m2][1], afr[0][m2][2], afr[0][m2][3],
                  sA + swz(offA0[m2]));
        #pragma unroll
        for (int p = 0; p < 4; ++p)
            LDSM4(bfr[0][p][0], bfr[0][p][1], bfr[0][p][2], bfr[0][p][3],
                  sB + swz(offB0[p]));

        #pragma unroll
        for (int ks = 0; ks < 4; ++ks) {
            const int cur = ks & 1;
            const int nxt = cur ^ 1;
            if (ks < 3) {   // prefetch ks+1 fragments while this ks computes
                #pragma unroll
                for (int m2 = 0; m2 < 4; ++m2)
                    LDSM4(afr[nxt][m2][0], afr[nxt][m2][1], afr[nxt][m2][2], afr[nxt][m2][3],
                          sA + swz(offA0[m2] + (ks + 1) * 32));
                #pragma unroll
                for (int p = 0; p < 4; ++p)
                    LDSM4(bfr[nxt][p][0], bfr[nxt][p][1], bfr[nxt][p][2], bfr[nxt][p][3],
                          sB + swz(offB0[p] + (ks + 1) * 32));
            }
            #pragma unroll
            for (int p = 0; p < 4; ++p) {
                #pragma unroll
                for (int m2 = 0; m2 < 4; ++m2) {
                    mma16816(acc[m2][2 * p],     afr[cur][m2], bfr[cur][p][0], bfr[cur][p][1]);
                    mma16816(acc[m2][2 * p + 1], afr[cur][m2], bfr[cur][p][2], bfr[cur][p][3]);
                }
            }
        }
    }

    // epilogue: out = acc * w_scale + bt[n]
    const float ws = *wscale;
    const int m0 = mt * BM + wm * 64 + (lane >> 2);
    const int n0 = nt * BN + wn * 64 + (lane & 3) * 2;
    #pragma unroll
    for (int nn = 0; nn < 8; ++nn) {
        const int n = n0 + nn * 8;
        const float bt0 = g_bt[n], bt1 = g_bt[n + 1];
        #pragma unroll
        for (int m2 = 0; m2 < 4; ++m2) {
            const int row = m0 + m2 * 16;
            float2 v0, v1;
            v0.x = acc[m2][nn][0] * ws + bt0;
            v0.y = acc[m2][nn][1] * ws + bt1;
            v1.x = acc[m2][nn][2] * ws + bt0;
            v1.y = acc[m2][nn][3] * ws + bt1;
            *reinterpret_cast<float2*>(out + (size_t)row * DOUT + n)       = v0;
            *reinterpret_cast<float2*>(out + (size_t)(row + 8) * DOUT + n) = v1;
        }
    }
}

// ---------------- launch ----------------
extern "C" void kernel_launch(void* const* d_in, const int* in_sizes, int n_in,
                              void* d_out, int out_size) {
    (void)in_sizes; (void)n_in; (void)out_size;
    const float* x      = (const float*)d_in[0];
    const float* W      = (const float*)d_in[1];
    const float* wscale = (const float*)d_in[2];
    const float* b      = (const float*)d_in[3];
    const float* bscale = (const float*)d_in[4];
    float* out = (float*)d_out;

    cudaFuncSetAttribute(k_gemm, cudaFuncAttributeMaxDynamicSharedMemorySize, SMEM_BYTES);

    k_init<<<1, 32>>>();
    k_absmax<<<2048, 256>>>((const float4*)W, (DOUT * DIN) / 4);
    k_tern<<<8192, 256>>>((const float4*)W);
    k_bt<<<1, 1024>>>(b, bscale);
    k_convx<<<16384, 256>>>((const float4*)x);
    k_gemm<<<MT_TILES * NT_TILES, THREADS, SMEM_BYTES>>>(wscale, out);
}

// round 8
// speedup vs baseline: 1.0550x; 1.0550x over previous
#include <cuda_runtime.h>
#include <cuda_fp16.h>
#include <cstdint>
#include <cstddef>

#define DI __device__ __forceinline__

// ---------------- problem constants ----------------
static constexpr int DIN   = 4096;
static constexpr int DOUT  = 4096;
static constexpr int MROWS = 8192;          // B*S = 4*2048

// ---------------- GEMM tiling (mma.sync path — tcgen05 is 'a'-gated, harness targets sm_103) ----
static constexpr int BM = 128;
static constexpr int BN = 128;
static constexpr int BK = 64;               // 128B fp16 rows
static constexpr int THREADS = 128;         // 4 warps: 2(M) x 2(N), warp tile 64x64
static constexpr int STAGES = 3;
static constexpr int STAGE_BYTES = (BM + BN) * BK * 2;      // 32 KB
static constexpr int SMEM_BYTES  = STAGES * STAGE_BYTES;    // 96 KB
static constexpr int NCH = DIN / BK;        // 64 K-chunks
static constexpr int MT_TILES = MROWS / BM; // 64
static constexpr int NT_TILES = DOUT / BN;  // 32

// fused prep kernel split point
static constexpr int TERN_BLOCKS  = (DOUT * DIN) / (8 * 256);   // 8192
static constexpr int CONVX_BLOCKS = (MROWS * DIN) / (8 * 256);  // 16384

// ---------------- device scratch (no allocations allowed) ----------------
__device__ __align__(128) __half g_A[(size_t)MROWS * DIN];   // 64 MB fp16 x
__device__ __align__(128) __half g_Wt[(size_t)DOUT * DIN];   // 32 MB fp16 ternary {-1,0,1}
__device__ float    g_bt[DOUT];
__device__ unsigned g_maxbits;

// ---------------- helpers ----------------
DI uint32_t smem_u32(const void* p) {
    uint32_t a;
    asm("{ .reg .u64 t; cvta.to.shared.u64 t, %1; cvt.u32.u64 %0, t; }"
        : "=r"(a) : "l"(p));
    return a;
}
DI uint32_t swz(uint32_t off) { return off ^ ((off >> 3) & 0x70); }  // SW128

DI void cp_async16(uint32_t saddr, const void* gaddr) {
    asm volatile("cp.async.cg.shared.global [%0], [%1], 16;" :: "r"(saddr), "l"(gaddr));
}

#define LDSM4(r0, r1, r2, r3, addr) \
    asm volatile("ldmatrix.sync.aligned.m8n8.x4.shared.b16 {%0,%1,%2,%3}, [%4];" \
                 : "=r"(r0), "=r"(r1), "=r"(r2), "=r"(r3) : "r"(addr))

DI void mma16816(float* c, const uint32_t* a, uint32_t b0, uint32_t b1) {
    asm volatile(
        "mma.sync.aligned.m16n8k16.row.col.f32.f16.f16.f32 "
        "{%0,%1,%2,%3}, {%4,%5,%6,%7}, {%8,%9}, {%0,%1,%2,%3};"
        : "+f"(c[0]), "+f"(c[1]), "+f"(c[2]), "+f"(c[3])
        : "r"(a[0]), "r"(a[1]), "r"(a[2]), "r"(a[3]), "r"(b0), "r"(b1));
}

// ---------------- prep kernels ----------------
// k_bt: ternarize bias (single block) AND init g_maxbits for the following absmax.
__global__ void k_bt(const float* __restrict__ b, const float* __restrict__ bscale) {
    __shared__ float red[1024];
    int tid = threadIdx.x;
    if (tid == 0) g_maxbits = 0u;          // runs before k_absmax on the stream
    float v[4];
    float m = 0.f;
    #pragma unroll
    for (int k = 0; k < 4; ++k) {
        v[k] = b[tid + k * 1024];
        m = fmaxf(m, fabsf(v[k]));
    }
    red[tid] = m;
    __syncthreads();
    for (int off = 512; off > 0; off >>= 1) {
        if (tid < off) red[tid] = fmaxf(red[tid], red[tid + off]);
        __syncthreads();
    }
    const float d = 0.05f * red[0];
    const float s = *bscale;
    #pragma unroll
    for (int k = 0; k < 4; ++k)
        g_bt[tid + k * 1024] = v[k] > d ? s : (v[k] < -d ? -s : 0.f);
}

__global__ void k_absmax(const float4* __restrict__ W, int n4) {
    int tid = threadIdx.x;
    float m = 0.f;
    for (int i = blockIdx.x * blockDim.x + tid; i < n4; i += gridDim.x * blockDim.x) {
        float4 v = W[i];
        m = fmaxf(m, fmaxf(fmaxf(fabsf(v.x), fabsf(v.y)), fmaxf(fabsf(v.z), fabsf(v.w))));
    }
    #pragma unroll
    for (int o = 16; o; o >>= 1) m = fmaxf(m, __shfl_xor_sync(0xffffffffu, m, o));
    __shared__ float sred[8];
    if ((tid & 31) == 0) sred[tid >> 5] = m;
    __syncthreads();
    if (tid == 0) {
        float mm = sred[0];
        #pragma unroll
        for (int w = 1; w < 8; ++w) mm = fmaxf(mm, sred[w]);
        atomicMax(&g_maxbits, __float_as_uint(mm));  // |.| >= 0 -> uint order == float order
    }
}

DI unsigned tern16(float v, float d) {
    return v > d ? 0x3C00u : (v < -d ? 0xBC00u : 0u);  // +1h / -1h / 0h
}
DI unsigned tpack(float x, float y, float d) {
    return tern16(x, d) | (tern16(y, d) << 16);
}
DI unsigned pack2h(float x, float y) {
    __half2 h = __floats2half2_rn(x, y);
    return *reinterpret_cast<unsigned*>(&h);
}

// fused: blocks [0, TERN_BLOCKS) ternarize W -> g_Wt; rest convert x -> g_A.
__global__ void k_fused(const float4* __restrict__ W, const float4* __restrict__ X) {
    if (blockIdx.x < TERN_BLOCKS) {
        const float d = 0.05f * __uint_as_float(g_maxbits);
        size_t i = (size_t)blockIdx.x * blockDim.x + threadIdx.x;
        float4 a = W[2 * i], c = W[2 * i + 1];
        uint4 o;
        o.x = tpack(a.x, a.y, d);
        o.y = tpack(a.z, a.w, d);
        o.z = tpack(c.x, c.y, d);
        o.w = tpack(c.z, c.w, d);
        reinterpret_cast<uint4*>(g_Wt)[i] = o;
    } else {
        size_t i = (size_t)(blockIdx.x - TERN_BLOCKS) * blockDim.x + threadIdx.x;
        float4 a = X[2 * i], c = X[2 * i + 1];
        uint4 o;
        o.x = pack2h(a.x, a.y);
        o.y = pack2h(a.z, a.w);
        o.z = pack2h(c.x, c.y);
        o.w = pack2h(c.z, c.w);
        reinterpret_cast<uint4*>(g_A)[i] = o;
    }
}

// ---------------- GEMM: 128x128x64, 4 warps, warp tile 64x64, 3-stage cp.async ----
// (R6 mainloop — fastest validated config; R7 manual reg double-buffer regressed.)
__global__ void __launch_bounds__(THREADS, 2)
k_gemm(const float* __restrict__ wscale, float* __restrict__ out) {
    extern __shared__ char smem[];
    const uint32_t sb = smem_u32(smem);
    const int tid  = threadIdx.x;
    const int lane = tid & 31;
    const int warp = tid >> 5;
    const int wm   = warp >> 1;   // 0..1  (M)
    const int wn   = warp & 1;    // 0..1  (N)
    const int nt   = blockIdx.x & (NT_TILES - 1);
    const int mt   = blockIdx.x >> 5;

    const __half* Ab = g_A  + (size_t)mt * BM * DIN;
    const __half* Bb = g_Wt + (size_t)nt * BN * DIN;

    const int lrA = lane & 15;                              // A row within m16
    const int lhA = (lane >> 4) * 16;                       // A k-byte half (0/16)
    const int nB  = ((lane >> 4) & 1) * 8 + (lane & 7);     // B row (n) within n16
    const int kB  = ((lane >> 3) & 1) * 16;                 // B k-byte half

    float acc[4][8][4];                                     // [m16][n8][frag]
    #pragma unroll
    for (int i = 0; i < 4; ++i)
        #pragma unroll
        for (int j = 0; j < 8; ++j)
            #pragma unroll
            for (int k = 0; k < 4; ++k) acc[i][j][k] = 0.f;

    auto issue_loads = [&](int s, int k0) {
        const uint32_t stg = sb + s * STAGE_BYTES;
        #pragma unroll
        for (int i = 0; i < 16; ++i) {
            int c = tid + i * THREADS;          // 0..2047 16B-chunks per stage
            int row = (c >> 3) & 127;
            int k8  = c & 7;
            const __half* gp;
            uint32_t bufo;
            if (c < 1024) { gp = Ab + (size_t)row * DIN + k0 + k8 * 8; bufo = 0; }
            else          { gp = Bb + (size_t)row * DIN + k0 + k8 * 8; bufo = BM * BK * 2; }
            cp_async16(stg + bufo + swz(row * 128 + k8 * 16), gp);
        }
    };

    // prefetch STAGES-1 stages
    #pragma unroll
    for (int s = 0; s < STAGES - 1; ++s) {
        issue_loads(s, s * BK);
        asm volatile("cp.async.commit_group;" ::: "memory");
    }

    for (int it = 0; it < NCH; ++it) {
        asm volatile("cp.async.wait_group %0;" :: "n"(STAGES - 2) : "memory");
        __syncthreads();   // stage 'it' ready everywhere; all warps past compute(it-1)

        int nx = it + STAGES - 1;
        if (nx < NCH) issue_loads(nx % STAGES, nx * BK);
        asm volatile("cp.async.commit_group;" ::: "memory");

        const uint32_t sA = sb + (it % STAGES) * STAGE_BYTES;
        const uint32_t sB = sA + BM * BK * 2;
        #pragma unroll
        for (int ks = 0; ks < 4; ++ks) {
            uint32_t a[4][4];
            #pragma unroll
            for (int m2 = 0; m2 < 4; ++m2) {
                uint32_t off = (uint32_t)(wm * 64 + m2 * 16 + lrA) * 128 + lhA + ks * 32;
                LDSM4(a[m2][0], a[m2][1], a[m2][2], a[m2][3], sA + swz(off));
            }
            #pragma unroll
            for (int p = 0; p < 4; ++p) {
                uint32_t b0, b1, b2, b3;
                uint32_t off = (uint32_t)(wn * 64 + p * 16 + nB) * 128 + kB + ks * 32;
                LDSM4(b0, b1, b2, b3, sB + swz(off));
                #pragma unroll
                for (int m2 = 0; m2 < 4; ++m2) {
                    mma16816(acc[m2][2 * p],     a[m2], b0, b1);
                    mma16816(acc[m2][2 * p + 1], a[m2], b2, b3);
                }
            }
        }
    }

    // epilogue: out = acc * w_scale + bt[n]; streaming stores (output is write-once)
    const float ws = *wscale;
    const int m0 = mt * BM + wm * 64 + (lane >> 2);
    const int n0 = nt * BN + wn * 64 + (lane & 3) * 2;
    #pragma unroll
    for (int nn = 0; nn < 8; ++nn) {
        const int n = n0 + nn * 8;
        const float bt0 = g_bt[n], bt1 = g_bt[n + 1];
        #pragma unroll
        for (int m2 = 0; m2 < 4; ++m2) {
            const int row = m0 + m2 * 16;
            float2 v0, v1;
            v0.x = acc[m2][nn][0] * ws + bt0;
            v0.y = acc[m2][nn][1] * ws + bt1;
            v1.x = acc[m2][nn][2] * ws + bt0;
            v1.y = acc[m2][nn][3] * ws + bt1;
            __stcs(reinterpret_cast<float2*>(out + (size_t)row * DOUT + n), v0);
            __stcs(reinterpret_cast<float2*>(out + (size_t)(row + 8) * DOUT + n), v1);
        }
    }
}

// ---------------- launch ----------------
// Order matters twofold: (a) k_bt zeroes g_maxbits before k_absmax;
// (b) k_gemm sits at kernel index 3 — the slot ncu has been capturing.
extern "C" void kernel_launch(void* const* d_in, const int* in_sizes, int n_in,
                              void* d_out, int out_size) {
    (void)in_sizes; (void)n_in; (void)out_size;
    const float* x      = (const float*)d_in[0];
    const float* W      = (const float*)d_in[1];
    const float* wscale = (const float*)d_in[2];
    const float* b      = (const float*)d_in[3];
    const float* bscale = (const float*)d_in[4];
    float* out = (float*)d_out;

    cudaFuncSetAttribute(k_gemm, cudaFuncAttributeMaxDynamicSharedMemorySize, SMEM_BYTES);

    k_bt<<<1, 1024>>>(b, bscale);                                   // idx 0 (+ maxbits init)
    k_absmax<<<2048, 256>>>((const float4*)W, (DOUT * DIN) / 4);    // idx 1
    k_fused<<<TERN_BLOCKS + CONVX_BLOCKS, 256>>>((const float4*)W,
                                                 (const float4*)x); // idx 2
    k_gemm<<<MT_TILES * NT_TILES, THREADS, SMEM_BYTES>>>(wscale, out); // idx 3
}

// round 9
// speedup vs baseline: 1.1224x; 1.0639x over previous
#include <cuda_runtime.h>
#include <cuda_fp16.h>
#include <cstdint>
#include <cstddef>

#define DI __device__ __forceinline__

// ---------------- problem constants ----------------
static constexpr int DIN   = 4096;
static constexpr int DOUT  = 4096;
static constexpr int MROWS = 8192;          // B*S = 4*2048

// ---------------- GEMM tiling (mma.sync path — tcgen05 is 'a'-gated, harness targets sm_103) ----
static constexpr int BM = 128;
static constexpr int BN = 128;
static constexpr int BK = 64;               // 128B fp16 rows
static constexpr int THREADS = 128;         // 4 warps: 2(M) x 2(N), warp tile 64x64
static constexpr int STAGES = 3;
static constexpr int STAGE_BYTES = (BM + BN) * BK * 2;      // 32 KB
static constexpr int SMEM_BYTES  = STAGES * STAGE_BYTES;    // 96 KB
static constexpr int NCH = DIN / BK;        // 64 K-chunks
static constexpr int MT_TILES = MROWS / BM; // 64
static constexpr int NT_TILES = DOUT / BN;  // 32

// fused prep kernel split point
static constexpr int TERN_BLOCKS  = (DOUT * DIN) / (8 * 256);   // 8192
static constexpr int CONVX_BLOCKS = (MROWS * DIN) / (8 * 256);  // 16384

// ---------------- device scratch (no allocations allowed) ----------------
__device__ __align__(128) __half g_A[(size_t)MROWS * DIN];   // 64 MB fp16 x
__device__ __align__(128) __half g_Wt[(size_t)DOUT * DIN];   // 32 MB fp16 ternary {-1,0,1}
__device__ float    g_bt[DOUT];
__device__ unsigned g_maxbits;

// ---------------- helpers ----------------
DI uint32_t smem_u32(const void* p) {
    uint32_t a;
    asm("{ .reg .u64 t; cvta.to.shared.u64 t, %1; cvt.u32.u64 %0, t; }"
        : "=r"(a) : "l"(p));
    return a;
}
DI uint32_t swz(uint32_t off) { return off ^ ((off >> 3) & 0x70); }  // SW128

DI void cp_async16(uint32_t saddr, const void* gaddr) {
    asm volatile("cp.async.cg.shared.global [%0], [%1], 16;" :: "r"(saddr), "l"(gaddr));
}

#define LDSM4(r0, r1, r2, r3, addr) \
    asm volatile("ldmatrix.sync.aligned.m8n8.x4.shared.b16 {%0,%1,%2,%3}, [%4];" \
                 : "=r"(r0), "=r"(r1), "=r"(r2), "=r"(r3) : "r"(addr))

DI void mma16816(float* c, const uint32_t* a, uint32_t b0, uint32_t b1) {
    asm volatile(
        "mma.sync.aligned.m16n8k16.row.col.f32.f16.f16.f32 "
        "{%0,%1,%2,%3}, {%4,%5,%6,%7}, {%8,%9}, {%0,%1,%2,%3};"
        : "+f"(c[0]), "+f"(c[1]), "+f"(c[2]), "+f"(c[3])
        : "r"(a[0]), "r"(a[1]), "r"(a[2]), "r"(a[3]), "r"(b0), "r"(b1));
}

// ---------------- prep kernels ----------------
// k_bt: ternarize bias (single block) AND init g_maxbits for the following absmax.
__global__ void k_bt(const float* __restrict__ b, const float* __restrict__ bscale) {
    __shared__ float red[1024];
    int tid = threadIdx.x;
    if (tid == 0) g_maxbits = 0u;          // runs before k_absmax on the stream
    float v[4];
    float m = 0.f;
    #pragma unroll
    for (int k = 0; k < 4; ++k) {
        v[k] = b[tid + k * 1024];
        m = fmaxf(m, fabsf(v[k]));
    }
    red[tid] = m;
    __syncthreads();
    for (int off = 512; off > 0; off >>= 1) {
        if (tid < off) red[tid] = fmaxf(red[tid], red[tid + off]);
        __syncthreads();
    }
    const float d = 0.05f * red[0];
    const float s = *bscale;
    #pragma unroll
    for (int k = 0; k < 4; ++k)
        g_bt[tid + k * 1024] = v[k] > d ? s : (v[k] < -d ? -s : 0.f);
}

__global__ void k_absmax(const float4* __restrict__ W, int n4) {
    int tid = threadIdx.x;
    float m = 0.f;
    for (int i = blockIdx.x * blockDim.x + tid; i < n4; i += gridDim.x * blockDim.x) {
        float4 v = W[i];
        m = fmaxf(m, fmaxf(fmaxf(fabsf(v.x), fabsf(v.y)), fmaxf(fabsf(v.z), fabsf(v.w))));
    }
    #pragma unroll
    for (int o = 16; o; o >>= 1) m = fmaxf(m, __shfl_xor_sync(0xffffffffu, m, o));
    __shared__ float sred[8];
    if ((tid & 31) == 0) sred[tid >> 5] = m;
    __syncthreads();
    if (tid == 0) {
        float mm = sred[0];
        #pragma unroll
        for (int w = 1; w < 8; ++w) mm = fmaxf(mm, sred[w]);
        atomicMax(&g_maxbits, __float_as_uint(mm));  // |.| >= 0 -> uint order == float order
    }
}

DI unsigned tern16(float v, float d) {
    return v > d ? 0x3C00u : (v < -d ? 0xBC00u : 0u);  // +1h / -1h / 0h
}
DI unsigned tpack(float x, float y, float d) {
    return tern16(x, d) | (tern16(y, d) << 16);
}
DI unsigned pack2h(float x, float y) {
    __half2 h = __floats2half2_rn(x, y);
    return *reinterpret_cast<unsigned*>(&h);
}

// fused: blocks [0, TERN_BLOCKS) ternarize W -> g_Wt; rest convert x -> g_A.
__global__ void k_fused(const float4* __restrict__ W, const float4* __restrict__ X) {
    if (blockIdx.x < TERN_BLOCKS) {
        const float d = 0.05f * __uint_as_float(g_maxbits);
        size_t i = (size_t)blockIdx.x * blockDim.x + threadIdx.x;
        float4 a = W[2 * i], c = W[2 * i + 1];
        uint4 o;
        o.x = tpack(a.x, a.y, d);
        o.y = tpack(a.z, a.w, d);
        o.z = tpack(c.x, c.y, d);
        o.w = tpack(c.z, c.w, d);
        reinterpret_cast<uint4*>(g_Wt)[i] = o;
    } else {
        size_t i = (size_t)(blockIdx.x - TERN_BLOCKS) * blockDim.x + threadIdx.x;
        float4 a = X[2 * i], c = X[2 * i + 1];
        uint4 o;
        o.x = pack2h(a.x, a.y);
        o.y = pack2h(a.z, a.w);
        o.z = pack2h(c.x, c.y);
        o.w = pack2h(c.z, c.w);
        reinterpret_cast<uint4*>(g_A)[i] = o;
    }
}

// ---------------- GEMM: 128x128x64, 4 warps, warp tile 64x64, 3-stage cp.async ----
// R9: ks=0 LDSMs issued BEFORE the next-stage cp.async burst, so tensor work
// covers the 16-instr LSU issue window after each barrier.
__global__ void __launch_bounds__(THREADS, 2)
k_gemm(const float* __restrict__ wscale, float* __restrict__ out) {
    extern __shared__ char smem[];
    const uint32_t sb = smem_u32(smem);
    const int tid  = threadIdx.x;
    const int lane = tid & 31;
    const int warp = tid >> 5;
    const int wm   = warp >> 1;   // 0..1  (M)
    const int wn   = warp & 1;    // 0..1  (N)
    const int nt   = blockIdx.x & (NT_TILES - 1);
    const int mt   = blockIdx.x >> 5;

    // ---- cp.async per-thread precompute (row0 = tid>>3, rows advance by 16) ----
    const int arow0 = tid >> 3;                   // 0..15
    const int k8    = tid & 7;
    const __half* gA = g_A  + ((size_t)(mt * BM + arow0)) * DIN + k8 * 8;
    const __half* gB = g_Wt + ((size_t)(nt * BN + arow0)) * DIN + k8 * 8;
    const uint32_t swSt = swz((uint32_t)arow0 * 128 + k8 * 16);  // same for A and B
    // (row += 16 -> +2048B, bits >= 11: swizzle XOR mask unchanged)

    auto issue_loads = [&](int s) {
        const uint32_t stA = sb + s * STAGE_BYTES + swSt;
        const uint32_t stB = stA + BM * BK * 2;
        #pragma unroll
        for (int j = 0; j < 8; ++j)
            cp_async16(stA + j * 2048, gA + (size_t)j * 16 * DIN);
        #pragma unroll
        for (int j = 0; j < 8; ++j)
            cp_async16(stB + j * 2048, gB + (size_t)j * 16 * DIN);
        gA += BK; gB += BK;                       // advance K for next call
    };

    // ---- LDSM per-thread precompute (pre-swizzle offsets have bits 5,6 clear,
    //      so per-ks address = base ^ (ks*32)) ----
    const int lrA = lane & 15;
    const int lhA = (lane >> 4) * 16;
    const int nB  = ((lane >> 4) & 1) * 8 + (lane & 7);
    const int kB  = ((lane >> 3) & 1) * 16;
    uint32_t swLA[4], swLB[4];
    #pragma unroll
    for (int m2 = 0; m2 < 4; ++m2)
        swLA[m2] = swz((uint32_t)(wm * 64 + m2 * 16 + lrA) * 128 + lhA);
    #pragma unroll
    for (int p = 0; p < 4; ++p)
        swLB[p] = swz((uint32_t)(wn * 64 + p * 16 + nB) * 128 + kB) + BM * BK * 2;

    float acc[4][8][4];                           // [m16][n8][frag]
    #pragma unroll
    for (int i = 0; i < 4; ++i)
        #pragma unroll
        for (int j = 0; j < 8; ++j)
            #pragma unroll
            for (int k = 0; k < 4; ++k) acc[i][j][k] = 0.f;

    // prefetch STAGES-1 stages
    #pragma unroll
    for (int s = 0; s < STAGES - 1; ++s) {
        issue_loads(s);
        asm volatile("cp.async.commit_group;" ::: "memory");
    }

    for (int it = 0; it < NCH; ++it) {
        asm volatile("cp.async.wait_group %0;" :: "n"(STAGES - 2) : "memory");
        __syncthreads();   // stage 'it' ready everywhere; all warps past compute(it-1)

        const uint32_t st = sb + (it % STAGES) * STAGE_BYTES;

        // ks=0 fragments FIRST — tensor work becomes available immediately
        uint32_t a0[4][4], b0[4][4];
        #pragma unroll
        for (int m2 = 0; m2 < 4; ++m2)
            LDSM4(a0[m2][0], a0[m2][1], a0[m2][2], a0[m2][3], st + swLA[m2]);
        #pragma unroll
        for (int p = 0; p < 4; ++p)
            LDSM4(b0[p][0], b0[p][1], b0[p][2], b0[p][3], st + swLB[p]);

        // next-stage gmem loads overlap with ks=0 MMAs below
        if (it + STAGES - 1 < NCH) issue_loads((it + STAGES - 1) % STAGES);
        asm volatile("cp.async.commit_group;" ::: "memory");

        // ks=0 MMAs (32 HMMA = ~256 cyc of tensor work covering the cp.async burst)
        #pragma unroll
        for (int p = 0; p < 4; ++p)
            #pragma unroll
            for (int m2 = 0; m2 < 4; ++m2) {
                mma16816(acc[m2][2 * p],     a0[m2], b0[p][0], b0[p][1]);
                mma16816(acc[m2][2 * p + 1], a0[m2], b0[p][2], b0[p][3]);
            }

        // ks = 1..3 (R6-style: LDSM then MMA, ptxas pipelines within the unroll)
        #pragma unroll
        for (int ks = 1; ks < 4; ++ks) {
            uint32_t a[4][4];
            #pragma unroll
            for (int m2 = 0; m2 < 4; ++m2)
                LDSM4(a[m2][0], a[m2][1], a[m2][2], a[m2][3],
                      st + (swLA[m2] ^ (ks * 32)));
            #pragma unroll
            for (int p = 0; p < 4; ++p) {
                uint32_t b0r, b1r, b2r, b3r;
                LDSM4(b0r, b1r, b2r, b3r, st + (swLB[p] ^ (ks * 32)));
                #pragma unroll
                for (int m2 = 0; m2 < 4; ++m2) {
                    mma16816(acc[m2][2 * p],     a[m2], b0r, b1r);
                    mma16816(acc[m2][2 * p + 1], a[m2], b2r, b3r);
                }
            }
        }
    }

    // epilogue: out = acc * w_scale + bt[n]; streaming stores (output is write-once)
    const float ws = *wscale;
    const int m0 = mt * BM + wm * 64 + (lane >> 2);
    const int n0 = nt * BN + wn * 64 + (lane & 3) * 2;
    #pragma unroll
    for (int nn = 0; nn < 8; ++nn) {
        const int n = n0 + nn * 8;
        const float bt0 = g_bt[n], bt1 = g_bt[n + 1];
        #pragma unroll
        for (int m2 = 0; m2 < 4; ++m2) {
            const int row = m0 + m2 * 16;
            float2 v0, v1;
            v0.x = acc[m2][nn][0] * ws + bt0;
            v0.y = acc[m2][nn][1] * ws + bt1;
            v1.x = acc[m2][nn][2] * ws + bt0;
            v1.y = acc[m2][nn][3] * ws + bt1;
            __stcs(reinterpret_cast<float2*>(out + (size_t)row * DOUT + n), v0);
            __stcs(reinterpret_cast<float2*>(out + (size_t)(row + 8) * DOUT + n), v1);
        }
    }
}

// ---------------- launch ----------------
// Order matters twofold: (a) k_bt zeroes g_maxbits before k_absmax;
// (b) k_gemm sits at kernel index 3 — the slot ncu captures.
extern "C" void kernel_launch(void* const* d_in, const int* in_sizes, int n_in,
                              void* d_out, int out_size) {
    (void)in_sizes; (void)n_in; (void)out_size;
    const float* x      = (const float*)d_in[0];
    const float* W      = (const float*)d_in[1];
    const float* wscale = (const float*)d_in[2];
    const float* b      = (const float*)d_in[3];
    const float* bscale = (const float*)d_in[4];
    float* out = (float*)d_out;

    cudaFuncSetAttribute(k_gemm, cudaFuncAttributeMaxDynamicSharedMemorySize, SMEM_BYTES);

    k_bt<<<1, 1024>>>(b, bscale);                                   // idx 0 (+ maxbits init)
    k_absmax<<<2048, 256>>>((const float4*)W, (DOUT * DIN) / 4);    // idx 1
    k_fused<<<TERN_BLOCKS + CONVX_BLOCKS, 256>>>((const float4*)W,
                                                 (const float4*)x); // idx 2
    k_gemm<<<MT_TILES * NT_TILES, THREADS, SMEM_BYTES>>>(wscale, out); // idx 3
}